// round 11
// baseline (speedup 1.0000x reference)
#include <cuda_runtime.h>
#include <cstdint>
#include <math.h>

// ---------------- problem constants ----------------
#define NROWS   65536
#define SDIM    256
#define ADIM    129
#define HID     256
#define NSTEP   30
#define EPS_LN  1e-5f

#define TM      32      // rows per CTA
#define RPW     8       // rows per warp (4 warps * 8 = 32)
#define XSTR    132     // padded float stride for x rows

// weight staging ring: 3 stages x 16 k-rows x 256 floats (16 KB/stage)
#define NSTG        3
#define STG_ROWS    16
#define STG_FLOATS  (STG_ROWS * 256)
#define STG_BYTES   (STG_FLOATS * 4)

typedef unsigned long long u64;

// packed fp32x2 helpers (sm_103a FFMA2)
__device__ __forceinline__ u64 pk2(float lo, float hi) {
    u64 r; asm("mov.b64 %0,{%1,%2};" : "=l"(r) : "f"(lo), "f"(hi)); return r;
}
__device__ __forceinline__ float2 up2(u64 v) {
    float lo, hi; asm("mov.b64 {%0,%1},%2;" : "=f"(lo), "=f"(hi) : "l"(v));
    float2 f; f.x = lo; f.y = hi; return f;
}
__device__ __forceinline__ void fma2(u64 &d, u64 a, u64 b) {
    asm("fma.rn.f32x2 %0,%1,%2,%0;" : "+l"(d) : "l"(a), "l"(b));
}

// cp.async helpers
__device__ __forceinline__ void cp16(uint32_t dst, const float* src) {
    asm volatile("cp.async.cg.shared.global [%0], [%1], 16;" :: "r"(dst), "l"(src));
}
__device__ __forceinline__ void cp_commit() {
    asm volatile("cp.async.commit_group;" ::: "memory");
}
template<int N> __device__ __forceinline__ void cp_wait() {
    asm volatile("cp.async.wait_group %0;" :: "n"(N) : "memory");
}
__device__ __forceinline__ uint32_t smem_u32(const void* p) {
    uint32_t a;
    asm("{ .reg .u64 t; cvta.to.shared.u64 t, %1; cvt.u32.u64 %0, t; }"
        : "=r"(a) : "l"(p));
    return a;
}

// W1 x-part (rows 256..384) zero-padded to 132 k-rows, stride 256
__device__ float g_W1xp[132 * HID];
// W3 zero-padded to 132 cols, stride 132
__device__ float g_W3p[HID * 132];
// S1 = state @ W1[0:256,:] + b1 (thread-private read/write, no sync needed)
__device__ float g_S1[(size_t)NROWS * HID];

__global__ void pack_kernel(const float* __restrict__ W1, const float* __restrict__ W3) {
    int i = blockIdx.x * blockDim.x + threadIdx.x;
    if (i < 132 * HID) {
        int k = i / HID, c = i - k * HID;
        g_W1xp[i] = (k < 129) ? W1[(size_t)(SDIM + k) * HID + c] : 0.0f;
    }
    if (i < HID * 132) {
        int k = i / 132, c = i - k * 132;
        g_W3p[i] = (c < ADIM) ? W3[k * ADIM + c] : 0.0f;
    }
}

// ---- cooperative stage fetch: nslots 16B-slots of a contiguous region ----
__device__ __forceinline__ void fetch_stage(uint32_t dst, const float* __restrict__ src,
                                            int nslots, int tid) {
    for (int s = tid; s < nslots; s += 128)
        cp16(dst + s * 16, src + (size_t)s * 4);
}

// ---- weights from smem stage buffer (stride 256): one 4-k block ----
__device__ __forceinline__ void loadw_s(u64 w[16], const float* __restrict__ buf,
                                        int b, int c0, int c1) {
    #pragma unroll
    for (int j = 0; j < 4; j++) {
        const float* p = buf + (b * 4 + j) * 256;
        const ulonglong2 a = *(const ulonglong2*)(p + c0);
        const ulonglong2 d = *(const ulonglong2*)(p + c1);
        w[4*j+0] = a.x; w[4*j+1] = a.y; w[4*j+2] = d.x; w[4*j+3] = d.y;
    }
}

// ---- activations: one 4-k block for 8 rows (broadcast LDS.128) ----
__device__ __forceinline__ void loadav(float4 av[RPW], const float* __restrict__ src,
                                       int sstr, int jb) {
    #pragma unroll
    for (int i = 0; i < RPW; i++)
        av[i] = *(const float4*)(src + i * sstr + jb * 4);
}

// ---- FMA one 4-k block ----
__device__ __forceinline__ void fmablock(const u64 w[16], const float4 av[RPW],
                                         u64 acc[RPW][4]) {
    #pragma unroll
    for (int j = 0; j < 4; j++) {
        #pragma unroll
        for (int i = 0; i < RPW; i++) {
            const float v = (j == 0) ? av[i].x : (j == 1) ? av[i].y
                          : (j == 2) ? av[i].z : av[i].w;
            const u64 xv = pk2(v, v);
            fma2(acc[i][0], w[4*j+0], xv);
            fma2(acc[i][1], w[4*j+1], xv);
            fma2(acc[i][2], w[4*j+2], xv);
            fma2(acc[i][3], w[4*j+3], xv);
        }
    }
}

// ---- staged GEMM, weight rows stride 256, full 256-wide output ----
template<int KROWS>
__device__ __forceinline__ void sgemm256(const float* __restrict__ Wg,
                                         const float* __restrict__ src, int sstr,
                                         u64 acc[RPW][4],
                                         float* __restrict__ ringf, uint32_t ringu,
                                         int tid, int c0, int c1)
{
    const int nst = (KROWS + STG_ROWS - 1) / STG_ROWS;
    __syncthreads();   // ring WAR vs previous gemm's consumers
    {
        int r0 = (KROWS < STG_ROWS) ? KROWS : STG_ROWS;
        fetch_stage(ringu, Wg, r0 * 64, tid);
        cp_commit();
        int r1 = KROWS - STG_ROWS; if (r1 > STG_ROWS) r1 = STG_ROWS;
        if (r1 > 0) fetch_stage(ringu + STG_BYTES, Wg + (size_t)STG_ROWS * 256, r1 * 64, tid);
        cp_commit();
    }
    int jbase = 0;
    #pragma unroll 1
    for (int st = 0; st < nst; st++) {
        if (st < nst - 1) cp_wait<1>(); else cp_wait<0>();
        __syncthreads();
        const float* buf = ringf + (st % NSTG) * STG_FLOATS;
        int rows = KROWS - st * STG_ROWS; if (rows > STG_ROWS) rows = STG_ROWS;
        const int nb = rows >> 2;
        #pragma unroll 1
        for (int b = 0; b < nb; b++) {
            u64 w[16];
            float4 av[RPW];
            loadw_s(w, buf, b, c0, c1);
            loadav(av, src, sstr, jbase + b);
            fmablock(w, av, acc);
        }
        jbase += nb;
        if (st + 2 < nst) {
            int fr = KROWS - (st + 2) * STG_ROWS; if (fr > STG_ROWS) fr = STG_ROWS;
            fetch_stage(ringu + ((st + 2) % NSTG) * STG_BYTES,
                        Wg + (size_t)(st + 2) * STG_ROWS * 256, fr * 64, tid);
            cp_commit();
        }
    }
}

// ---- staged GEMM for W3 (rows stride 132, 128-wide output: 4 cols/lane) ----
__device__ __forceinline__ void loadw3_s(u64 w[8], const float* __restrict__ buf,
                                         int b, int c0) {
    #pragma unroll
    for (int j = 0; j < 4; j++) {
        const ulonglong2 a = *(const ulonglong2*)(buf + (b * 4 + j) * 132 + c0);
        w[2*j] = a.x; w[2*j+1] = a.y;
    }
}
__device__ __forceinline__ void fmablock3(const u64 w[8], const float4 av[RPW],
                                          u64 acc[RPW][2]) {
    #pragma unroll
    for (int j = 0; j < 4; j++) {
        #pragma unroll
        for (int i = 0; i < RPW; i++) {
            const float v = (j == 0) ? av[i].x : (j == 1) ? av[i].y
                          : (j == 2) ? av[i].z : av[i].w;
            const u64 xv = pk2(v, v);
            fma2(acc[i][0], w[2*j],   xv);
            fma2(acc[i][1], w[2*j+1], xv);
        }
    }
}
__device__ __forceinline__ void sgemm132(const float* __restrict__ src,
                                         u64 acc[RPW][2],
                                         float* __restrict__ ringf, uint32_t ringu,
                                         int tid, int c0)
{
    const int KROWS = 256;
    const int nst = KROWS / STG_ROWS;       // 16
    const int slots = STG_ROWS * 33;        // 16 rows * 132 floats / 4
    __syncthreads();
    fetch_stage(ringu, g_W3p, slots, tid);
    cp_commit();
    fetch_stage(ringu + STG_BYTES, g_W3p + STG_ROWS * 132, slots, tid);
    cp_commit();
    int jbase = 0;
    #pragma unroll 1
    for (int st = 0; st < nst; st++) {
        if (st < nst - 1) cp_wait<1>(); else cp_wait<0>();
        __syncthreads();
        const float* buf = ringf + (st % NSTG) * STG_FLOATS;
        #pragma unroll 1
        for (int b = 0; b < STG_ROWS / 4; b++) {
            u64 w[8];
            float4 av[RPW];
            loadw3_s(w, buf, b, c0);
            loadav(av, src, HID, jbase + b);
            fmablock3(w, av, acc);
        }
        jbase += STG_ROWS / 4;
        if (st + 2 < nst) {
            fetch_stage(ringu + ((st + 2) % NSTG) * STG_BYTES,
                        g_W3p + (size_t)(st + 2) * STG_ROWS * 132, slots, tid);
            cp_commit();
        }
    }
}

// LayerNorm (two-pass) + ReLU + store to smem (stride 256)
__device__ __forceinline__ void ln_relu_store(u64 acc[RPW][4], float* __restrict__ dst,
                                              const float* __restrict__ g,
                                              const float* __restrict__ be,
                                              int c0, int c1)
{
    const float4 ga = *(const float4*)(g + c0);
    const float4 gb = *(const float4*)(g + c1);
    const float4 ba = *(const float4*)(be + c0);
    const float4 bb = *(const float4*)(be + c1);
    #pragma unroll
    for (int i = 0; i < RPW; i++) {
        float2 a0 = up2(acc[i][0]), a1 = up2(acc[i][1]);
        float2 a2 = up2(acc[i][2]), a3 = up2(acc[i][3]);
        float s = ((a0.x + a0.y) + (a1.x + a1.y)) + ((a2.x + a2.y) + (a3.x + a3.y));
        #pragma unroll
        for (int o = 16; o > 0; o >>= 1) s += __shfl_xor_sync(0xffffffffu, s, o);
        const float m = s * (1.0f / 256.0f);
        const float d0 = a0.x - m, d1 = a0.y - m, d2 = a1.x - m, d3 = a1.y - m;
        const float d4 = a2.x - m, d5 = a2.y - m, d6 = a3.x - m, d7 = a3.y - m;
        float ss = ((d0*d0 + d1*d1) + (d2*d2 + d3*d3)) + ((d4*d4 + d5*d5) + (d6*d6 + d7*d7));
        #pragma unroll
        for (int o = 16; o > 0; o >>= 1) ss += __shfl_xor_sync(0xffffffffu, ss, o);
        const float inv = rsqrtf(ss * (1.0f / 256.0f) + EPS_LN);
        float4 h0, h1;
        h0.x = fmaxf(d0 * inv * ga.x + ba.x, 0.0f);
        h0.y = fmaxf(d1 * inv * ga.y + ba.y, 0.0f);
        h0.z = fmaxf(d2 * inv * ga.z + ba.z, 0.0f);
        h0.w = fmaxf(d3 * inv * ga.w + ba.w, 0.0f);
        h1.x = fmaxf(d4 * inv * gb.x + bb.x, 0.0f);
        h1.y = fmaxf(d5 * inv * gb.y + bb.y, 0.0f);
        h1.z = fmaxf(d6 * inv * gb.z + bb.z, 0.0f);
        h1.w = fmaxf(d7 * inv * gb.w + bb.w, 0.0f);
        *(float4*)(dst + i * HID + c0) = h0;
        *(float4*)(dst + i * HID + c1) = h1;
    }
}

// smem: ring 3*4096 + h 32*256 + x 32*132 = 24704 floats = 98816 B -> 2 CTAs/SM
#define RINGF (NSTG * STG_FLOATS)
#define HBF   (TM * HID)
#define XSF   (TM * XSTR)
#define SMEM_BYTES ((RINGF + HBF + XSF) * sizeof(float))

__global__ void __launch_bounds__(128, 2)
actor_kernel(const float* __restrict__ state,  const float* __restrict__ amask,
             const float* __restrict__ x_init, const float* __restrict__ gumbel,
             const float* __restrict__ W1,     const float* __restrict__ b1,
             const float* __restrict__ g1,     const float* __restrict__ be1,
             const float* __restrict__ W2,     const float* __restrict__ b2,
             const float* __restrict__ g2,     const float* __restrict__ be2,
             const float* __restrict__ b3,     float* __restrict__ out)
{
    extern __shared__ float sm[];
    float* ringf = sm;                 // [3][16*256] weight stage ring
    float* hb    = sm + RINGF;         // [TM][256] h buffer
    float* xs    = sm + RINGF + HBF;   // [TM][132] x

    const uint32_t ringu = smem_u32(ringf);
    const int tid   = threadIdx.x;
    const int lane  = tid & 31;
    const int wid   = tid >> 5;
    const int rbase = wid * RPW;
    const size_t grow0 = (size_t)blockIdx.x * TM;
    const int c0 = lane * 4;
    const int c1 = 128 + lane * 4;

    float* xw  = xs + rbase * XSTR;
    float* hw  = hb + rbase * HID;
    float* s1w = g_S1 + (grow0 + rbase) * HID;   // global, thread-private access

    // ---- load x rows (stride 129, scalar coalesced) + zero pads ----
    #pragma unroll
    for (int i = 0; i < RPW; i++) {
        const size_t gr = grow0 + rbase + i;
        const float* xp = x_init + gr * ADIM;
        #pragma unroll
        for (int j = 0; j < 4; j++) xw[i * XSTR + lane + 32 * j] = xp[lane + 32 * j];
        if (lane == 0) xw[i * XSTR + 128] = xp[128];
        if (lane >= 1 && lane <= 3) xw[i * XSTR + 128 + lane] = 0.0f;
    }
    // ---- stage state rows in hb ----
    #pragma unroll
    for (int i = 0; i < RPW; i++) {
        const float* sp = state + (grow0 + rbase + i) * SDIM;
        *(float4*)(hw + i * HID + c0) = *(const float4*)(sp + c0);
        *(float4*)(hw + i * HID + c1) = *(const float4*)(sp + c1);
    }
    __syncwarp();

    // step-invariant preloads
    float w128[8];  // W3 col 128, lane-strided over k
    #pragma unroll
    for (int j = 0; j < 8; j++) w128[j] = g_W3p[(size_t)(lane + 32 * j) * 132 + 128];
    const float b3L = __ldg(b3 + 128);

    u64 acc[RPW][4];

    // ---- S1 = state @ W1[0:256,:] + b1 (hoisted), spill to g_S1 ----
    {
        const float4 ba = *(const float4*)(b1 + c0);
        const float4 bb = *(const float4*)(b1 + c1);
        #pragma unroll
        for (int i = 0; i < RPW; i++) {
            acc[i][0] = pk2(ba.x, ba.y); acc[i][1] = pk2(ba.z, ba.w);
            acc[i][2] = pk2(bb.x, bb.y); acc[i][3] = pk2(bb.z, bb.w);
        }
        sgemm256<256>(W1, hw, HID, acc, ringf, ringu, tid, c0, c1);
        #pragma unroll
        for (int i = 0; i < RPW; i++) {
            float2 a0 = up2(acc[i][0]), a1 = up2(acc[i][1]);
            float2 a2 = up2(acc[i][2]), a3 = up2(acc[i][3]);
            float4 v0; v0.x = a0.x; v0.y = a0.y; v0.z = a1.x; v0.w = a1.y;
            float4 v1; v1.x = a2.x; v1.y = a2.y; v1.z = a3.x; v1.w = a3.y;
            *(float4*)(s1w + i * HID + c0) = v0;
            *(float4*)(s1w + i * HID + c1) = v1;
        }
    }

    // ---- 30 diffusion steps ----
    for (int s = 0; s < NSTEP; s++) {
        const float t = (float)(NSTEP - 1 - s);

        // layer 1: acc = S1 + t*W1[385]; += x @ W1x (K=132); LN+ReLU -> hb
        {
            const float4 wa = *(const float4*)(W1 + (size_t)385 * HID + c0);
            const float4 wb = *(const float4*)(W1 + (size_t)385 * HID + c1);
            #pragma unroll
            for (int i = 0; i < RPW; i++) {
                const float4 sa = *(const float4*)(s1w + i * HID + c0);
                const float4 sb = *(const float4*)(s1w + i * HID + c1);
                acc[i][0] = pk2(fmaf(t, wa.x, sa.x), fmaf(t, wa.y, sa.y));
                acc[i][1] = pk2(fmaf(t, wa.z, sa.z), fmaf(t, wa.w, sa.w));
                acc[i][2] = pk2(fmaf(t, wb.x, sb.x), fmaf(t, wb.y, sb.y));
                acc[i][3] = pk2(fmaf(t, wb.z, sb.z), fmaf(t, wb.w, sb.w));
            }
            sgemm256<132>(g_W1xp, xw, XSTR, acc, ringf, ringu, tid, c0, c1);
            ln_relu_store(acc, hw, g1, be1, c0, c1);
        }

        // layer 2: acc = b2; += h1 @ W2; LN+ReLU -> hb
        {
            const float4 ba = *(const float4*)(b2 + c0);
            const float4 bb = *(const float4*)(b2 + c1);
            #pragma unroll
            for (int i = 0; i < RPW; i++) {
                acc[i][0] = pk2(ba.x, ba.y); acc[i][1] = pk2(ba.z, ba.w);
                acc[i][2] = pk2(bb.x, bb.y); acc[i][3] = pk2(bb.z, bb.w);
            }
            sgemm256<256>(W2, hw, HID, acc, ringf, ringu, tid, c0, c1);
            __syncwarp();
            ln_relu_store(acc, hw, g2, be2, c0, c1);
        }

        // layer 3: noise = h2 @ W3 + b3; x -= 0.1*noise
        {
            u64 a3[RPW][2];
            const float4 b3v = *(const float4*)(b3 + c0);
            #pragma unroll
            for (int i = 0; i < RPW; i++) {
                a3[i][0] = pk2(b3v.x, b3v.y);
                a3[i][1] = pk2(b3v.z, b3v.w);
            }
            sgemm132(hw, a3, ringf, ringu, tid, c0);
            // col 128: lane-strided partial dot + butterfly reduce per row
            float a128[RPW];
            #pragma unroll
            for (int i = 0; i < RPW; i++) a128[i] = 0.0f;
            #pragma unroll
            for (int j = 0; j < 8; j++) {
                #pragma unroll
                for (int i = 0; i < RPW; i++) {
                    const float hv = hw[i * HID + lane + 32 * j];
                    a128[i] = fmaf(hv, w128[j], a128[i]);
                }
            }
            #pragma unroll
            for (int i = 0; i < RPW; i++) {
                #pragma unroll
                for (int o = 16; o > 0; o >>= 1)
                    a128[i] += __shfl_xor_sync(0xffffffffu, a128[i], o);
            }
            // x update
            #pragma unroll
            for (int i = 0; i < RPW; i++) {
                float4 xo = *(float4*)(xw + i * XSTR + c0);
                const float2 n0 = up2(a3[i][0]), n1 = up2(a3[i][1]);
                xo.x -= 0.1f * n0.x;
                xo.y -= 0.1f * n0.y;
                xo.z -= 0.1f * n1.x;
                xo.w -= 0.1f * n1.y;
                *(float4*)(xw + i * XSTR + c0) = xo;
                if (lane == 0)
                    xw[i * XSTR + 128] -= 0.1f * (b3L + a128[i]);
            }
        }
        __syncwarp();
    }

    // ---- epilogue: masked gumbel softmax argmax (straight-through) + tanh ----
    #pragma unroll
    for (int i = 0; i < RPW; i++) {
        const size_t gr = grow0 + rbase + i;
        const float4 xv = *(const float4*)(xw + i * XSTR + c0);
        const float4 mk = *(const float4*)(amask  + gr * 128 + c0);
        const float4 gn = *(const float4*)(gumbel + gr * 128 + c0);
        float z[4];
        z[0] = xv.x + (1.0f - mk.x) * (-1e9f) + gn.x;
        z[1] = xv.y + (1.0f - mk.y) * (-1e9f) + gn.y;
        z[2] = xv.z + (1.0f - mk.z) * (-1e9f) + gn.z;
        z[3] = xv.w + (1.0f - mk.w) * (-1e9f) + gn.w;
        float best = z[0]; int bi = c0;
        #pragma unroll
        for (int j = 1; j < 4; j++) if (z[j] > best) { best = z[j]; bi = c0 + j; }
        #pragma unroll
        for (int o = 16; o > 0; o >>= 1) {
            float ov = __shfl_xor_sync(0xffffffffu, best, o);
            int   oi = __shfl_xor_sync(0xffffffffu, bi,   o);
            if (ov > best || (ov == best && oi < bi)) { best = ov; bi = oi; }
        }
        float e[4]; float sl = 0.0f;
        #pragma unroll
        for (int j = 0; j < 4; j++) { e[j] = expf(z[j] - best); sl += e[j]; }
        #pragma unroll
        for (int o = 16; o > 0; o >>= 1) sl += __shfl_xor_sync(0xffffffffu, sl, o);
        #pragma unroll
        for (int j = 0; j < 4; j++) {
            const float p  = e[j] / sl;
            const float yh = (c0 + j == bi) ? 1.0f : 0.0f;
            const float tv = yh + p;
            out[gr * ADIM + c0 + j] = tv - p;
        }
        if (lane == 0) out[gr * ADIM + 128] = tanhf(xw[i * XSTR + 128]);
    }
}

extern "C" void kernel_launch(void* const* d_in, const int* in_sizes, int n_in,
                              void* d_out, int out_size)
{
    const float* state  = (const float*)d_in[0];
    const float* amask  = (const float*)d_in[1];
    const float* x_init = (const float*)d_in[2];
    const float* gumbel = (const float*)d_in[3];
    const float* W1     = (const float*)d_in[4];
    const float* b1     = (const float*)d_in[5];
    const float* g1     = (const float*)d_in[6];
    const float* be1    = (const float*)d_in[7];
    const float* W2     = (const float*)d_in[8];
    const float* b2     = (const float*)d_in[9];
    const float* g2     = (const float*)d_in[10];
    const float* be2    = (const float*)d_in[11];
    const float* W3     = (const float*)d_in[12];
    const float* b3     = (const float*)d_in[13];
    float* out          = (float*)d_out;

    pack_kernel<<<(132 * HID + 255) / 256, 256>>>(W1, W3);

    cudaFuncSetAttribute(actor_kernel,
                         cudaFuncAttributeMaxDynamicSharedMemorySize,
                         (int)SMEM_BYTES);

    actor_kernel<<<NROWS / TM, 128, SMEM_BYTES>>>(
        state, amask, x_init, gumbel,
        W1, b1, g1, be1, W2, b2, g2, be2, b3, out);
}

// round 14
// speedup vs baseline: 1.4756x; 1.4756x over previous
#include <cuda_runtime.h>
#include <cstdint>
#include <math.h>

// ---------------- problem constants ----------------
#define NROWS   65536
#define SDIM    256
#define ADIM    129
#define HID     256
#define NSTEP   30
#define EPS_LN  1e-5f

#define TM      64      // rows per CTA
#define WROWS   16      // rows per warp (m16 tiles)
#define NW      4
#define HS      260     // h smem stride (260%32=4 -> conflict-free A-frag LDS)
#define XS      140     // x smem stride
#define NT      32      // n-tiles for N=256
#define NTP     16      // nt pairs
#define NT3     18      // n-tiles for W3 (N padded 129->144)
#define NTP3    9
#define KT      32      // k-tiles for K=256
#define KT1     17      // k-tiles for K=136 (x part, 129 padded)

typedef unsigned int u32;

// ---------------- tf32 helpers ----------------
__device__ __forceinline__ u32 cvt_tf32(float x) {
    u32 r; asm("cvt.rna.tf32.f32 %0, %1;" : "=r"(r) : "f"(x)); return r;
}
__device__ __forceinline__ void mma8(float* c, const u32 a[4], u32 b0, u32 b1) {
    asm("mma.sync.aligned.m16n8k8.row.col.f32.tf32.tf32.f32 "
        "{%0,%1,%2,%3},{%4,%5,%6,%7},{%8,%9},{%0,%1,%2,%3};"
        : "+f"(c[0]), "+f"(c[1]), "+f"(c[2]), "+f"(c[3])
        : "r"(a[0]), "r"(a[1]), "r"(a[2]), "r"(a[3]), "r"(b0), "r"(b1));
}

// ---------------- weight fragment streams (hi/lo tf32 split) ----------------
__device__ float g_W1s_hi[KT  * NTP  * 32 * 4];  // state part of W1
__device__ float g_W1s_lo[KT  * NTP  * 32 * 4];
__device__ float g_W1x_hi[KT1 * NTP  * 32 * 4];  // x part of W1
__device__ float g_W1x_lo[KT1 * NTP  * 32 * 4];
__device__ float g_W2_hi [KT  * NTP  * 32 * 4];
__device__ float g_W2_lo [KT  * NTP  * 32 * 4];
__device__ float g_W3_hi [KT  * NTP3 * 32 * 4];  // K=256, N padded to 144
__device__ float g_W3_lo [KT  * NTP3 * 32 * 4];
__device__ float g_b3p[NT3 * 8];                 // b3 zero-padded to 144
// per-warp-tile S1 fragments (thread-private roundtrip, frag order)
__device__ float g_S1f[(size_t)(NROWS / WROWS) * NT * 32 * 4];  // 64 MB

// fragment pack; dst selected in device code (no host symbol-address APIs)
__global__ void pack_frag(const float* __restrict__ src, int which, int stride,
                          int validK, int validN, int ktn, int ntpn, int kOff)
{
    float *hi, *lo;
    switch (which) {
        case 0: hi = g_W1s_hi; lo = g_W1s_lo; break;
        case 1: hi = g_W1x_hi; lo = g_W1x_lo; break;
        case 2: hi = g_W2_hi;  lo = g_W2_lo;  break;
        default: hi = g_W3_hi; lo = g_W3_lo;  break;
    }
    int i = blockIdx.x * 256 + threadIdx.x;
    int total = ktn * ntpn * 32;
    if (i >= total) return;
    int lane = i & 31, rest = i >> 5;
    int p = rest % ntpn, kt = rest / ntpn;
    int q = lane & 3, tq = lane >> 2;
    int k0 = kt * 8 + q, k1 = k0 + 4;
    int c0 = (2 * p) * 8 + tq, c1 = (2 * p + 1) * 8 + tq;
    float v[4];
    v[0] = (k0 < validK && c0 < validN) ? src[(size_t)(k0 + kOff) * stride + c0] : 0.0f;
    v[1] = (k1 < validK && c0 < validN) ? src[(size_t)(k1 + kOff) * stride + c0] : 0.0f;
    v[2] = (k0 < validK && c1 < validN) ? src[(size_t)(k0 + kOff) * stride + c1] : 0.0f;
    v[3] = (k1 < validK && c1 < validN) ? src[(size_t)(k1 + kOff) * stride + c1] : 0.0f;
    float H[4], L[4];
    #pragma unroll
    for (int j = 0; j < 4; j++) {
        u32 h = cvt_tf32(v[j]);
        H[j] = __uint_as_float(h);
        L[j] = __uint_as_float(cvt_tf32(v[j] - __uint_as_float(h)));
    }
    float4 Hv; Hv.x = H[0]; Hv.y = H[1]; Hv.z = H[2]; Hv.w = H[3];
    float4 Lv; Lv.x = L[0]; Lv.y = L[1]; Lv.z = L[2]; Lv.w = L[3];
    ((float4*)hi)[i] = Hv;
    ((float4*)lo)[i] = Lv;
}
__global__ void pack_b3(const float* __restrict__ b3) {
    int i = threadIdx.x;
    if (i < NT3 * 8) g_b3p[i] = (i < ADIM) ? b3[i] : 0.0f;
}

// ---------------- core GEMM: C[M16 x N] += A @ B (3xTF32) ----------------
template<int KTN, int NTPN>
__device__ __forceinline__ void gemm_frag(float* cfr, const float* __restrict__ A,
                                          int astr, const float* __restrict__ Bh,
                                          const float* __restrict__ Bl, int lane)
{
    const int q = lane & 3, tq = lane >> 2;
    #pragma unroll 1
    for (int kt = 0; kt < KTN; kt++) {
        const int k0 = kt * 8 + q;
        const float a0 = A[tq * astr + k0];
        const float a1 = A[(tq + 8) * astr + k0];
        const float a2 = A[tq * astr + k0 + 4];
        const float a3 = A[(tq + 8) * astr + k0 + 4];
        u32 ah[4], al[4];
        ah[0] = cvt_tf32(a0); al[0] = cvt_tf32(a0 - __uint_as_float(ah[0]));
        ah[1] = cvt_tf32(a1); al[1] = cvt_tf32(a1 - __uint_as_float(ah[1]));
        ah[2] = cvt_tf32(a2); al[2] = cvt_tf32(a2 - __uint_as_float(ah[2]));
        ah[3] = cvt_tf32(a3); al[3] = cvt_tf32(a3 - __uint_as_float(ah[3]));
        const float4* bh = (const float4*)Bh + (size_t)kt * NTPN * 32 + lane;
        const float4* bl = (const float4*)Bl + (size_t)kt * NTPN * 32 + lane;
        #pragma unroll
        for (int p = 0; p < NTPN; p++) {
            const float4 h4 = bh[p * 32];
            const float4 l4 = bl[p * 32];
            float* cc = cfr + p * 8;
            const u32 h0 = __float_as_uint(h4.x), h1 = __float_as_uint(h4.y);
            const u32 h2 = __float_as_uint(h4.z), h3 = __float_as_uint(h4.w);
            const u32 l0 = __float_as_uint(l4.x), l1 = __float_as_uint(l4.y);
            const u32 l2 = __float_as_uint(l4.z), l3 = __float_as_uint(l4.w);
            mma8(cc,     ah, h0, h1);
            mma8(cc,     ah, l0, l1);
            mma8(cc,     al, h0, h1);
            mma8(cc + 4, ah, h2, h3);
            mma8(cc + 4, ah, l2, l3);
            mma8(cc + 4, al, h2, h3);
        }
    }
}

// ---------------- LayerNorm + ReLU on C fragments -> h smem ----------------
__device__ __forceinline__ void ln_relu_frag(const float* cfr, float* __restrict__ hw,
                                             const float* __restrict__ g,
                                             const float* __restrict__ be, int lane)
{
    const int q = lane & 3, tq = lane >> 2;
    float s0 = 0.0f, s1 = 0.0f;
    #pragma unroll
    for (int nt = 0; nt < NT; nt++) {
        s0 += cfr[4 * nt] + cfr[4 * nt + 1];
        s1 += cfr[4 * nt + 2] + cfr[4 * nt + 3];
    }
    s0 += __shfl_xor_sync(0xffffffffu, s0, 1); s0 += __shfl_xor_sync(0xffffffffu, s0, 2);
    s1 += __shfl_xor_sync(0xffffffffu, s1, 1); s1 += __shfl_xor_sync(0xffffffffu, s1, 2);
    const float m0 = s0 * (1.0f / 256.0f), m1 = s1 * (1.0f / 256.0f);
    float v0 = 0.0f, v1 = 0.0f;
    #pragma unroll
    for (int nt = 0; nt < NT; nt++) {
        float d0 = cfr[4 * nt] - m0,     d1 = cfr[4 * nt + 1] - m0;
        float d2 = cfr[4 * nt + 2] - m1, d3 = cfr[4 * nt + 3] - m1;
        v0 += d0 * d0 + d1 * d1;
        v1 += d2 * d2 + d3 * d3;
    }
    v0 += __shfl_xor_sync(0xffffffffu, v0, 1); v0 += __shfl_xor_sync(0xffffffffu, v0, 2);
    v1 += __shfl_xor_sync(0xffffffffu, v1, 1); v1 += __shfl_xor_sync(0xffffffffu, v1, 2);
    const float i0 = rsqrtf(v0 * (1.0f / 256.0f) + EPS_LN);
    const float i1 = rsqrtf(v1 * (1.0f / 256.0f) + EPS_LN);
    #pragma unroll
    for (int nt = 0; nt < NT; nt++) {
        const int col = nt * 8 + 2 * q;
        const float2 gg = *(const float2*)(g + col);
        const float2 bb = *(const float2*)(be + col);
        float2 ha, hb2;
        ha.x  = fmaxf(fmaf((cfr[4 * nt]     - m0) * i0, gg.x, bb.x), 0.0f);
        ha.y  = fmaxf(fmaf((cfr[4 * nt + 1] - m0) * i0, gg.y, bb.y), 0.0f);
        hb2.x = fmaxf(fmaf((cfr[4 * nt + 2] - m1) * i1, gg.x, bb.x), 0.0f);
        hb2.y = fmaxf(fmaf((cfr[4 * nt + 3] - m1) * i1, gg.y, bb.y), 0.0f);
        *(float2*)(hw + tq * HS + col)       = ha;
        *(float2*)(hw + (tq + 8) * HS + col) = hb2;
    }
}

// smem: consts 8*256 + h 64*260 + x 64*140 = 27648 floats = 110592 B -> 2 CTAs/SM
#define CBF   (8 * 256)
#define HBF   (TM * HS)
#define XBF   (TM * XS)
#define SMEM_BYTES ((CBF + HBF + XBF) * sizeof(float))

__global__ void __launch_bounds__(128, 2)
actor_kernel(const float* __restrict__ state,  const float* __restrict__ amask,
             const float* __restrict__ x_init, const float* __restrict__ gumbel,
             const float* __restrict__ W1,     const float* __restrict__ b1,
             const float* __restrict__ g1,     const float* __restrict__ be1,
             const float* __restrict__ W2,     const float* __restrict__ b2,
             const float* __restrict__ g2,     const float* __restrict__ be2,
             const float* __restrict__ b3,     float* __restrict__ out)
{
    extern __shared__ float sm[];
    float* cb = sm;               // [8][256]: g1,be1,g2,be2,b2,b3p,w385,b1
    float* hb = sm + CBF;         // [64][260]
    float* xb = sm + CBF + HBF;   // [64][140]

    const int tid  = threadIdx.x;
    const int lane = tid & 31;
    const int wid  = tid >> 5;
    const int q    = lane & 3, tq = lane >> 2;
    const int wr   = wid * WROWS;
    const size_t grow0 = (size_t)blockIdx.x * TM;
    float* hw = hb + wr * HS;
    float* xw = xb + wr * XS;
    const int warpgid = blockIdx.x * NW + wid;
    float* s1p = g_S1f + (size_t)warpgid * (NT * 32 * 4);

    // ---- stage per-layer constants into smem ----
    for (int i = tid; i < 256; i += 128) {
        cb[0 * 256 + i] = g1[i];
        cb[1 * 256 + i] = be1[i];
        cb[2 * 256 + i] = g2[i];
        cb[3 * 256 + i] = be2[i];
        cb[4 * 256 + i] = b2[i];
        cb[5 * 256 + i] = (i < NT3 * 8) ? g_b3p[i] : 0.0f;
        cb[6 * 256 + i] = W1[(size_t)385 * HID + i];
        cb[7 * 256 + i] = b1[i];
    }
    __syncthreads();

    // ---- stage x rows (stride 129) and state rows (each warp its 16 rows) ----
    #pragma unroll 1
    for (int i = 0; i < WROWS; i++) {
        const size_t gr = grow0 + wr + i;
        const float* xp = x_init + gr * ADIM;
        #pragma unroll
        for (int j = 0; j < 4; j++) xw[i * XS + lane + 32 * j] = xp[lane + 32 * j];
        if (lane == 0) xw[i * XS + 128] = xp[128];
        if (lane >= 1 && lane <= 11) xw[i * XS + 128 + lane] = 0.0f;
        const float* sp = state + gr * SDIM;
        *(float4*)(hw + i * HS + lane * 4)       = *(const float4*)(sp + lane * 4);
        *(float4*)(hw + i * HS + 128 + lane * 4) = *(const float4*)(sp + 128 + lane * 4);
    }
    __syncwarp();

    float cfr[NT * 4];   // C fragments: [nt]{c0,c1,c2,c3}

    // ---- S1 = state @ W1[0:256] + b1 -> g_S1f (frag order, thread-private) ----
    #pragma unroll
    for (int nt = 0; nt < NT; nt++) {
        const float2 bb = *(const float2*)(cb + 7 * 256 + nt * 8 + 2 * q);
        cfr[4 * nt] = bb.x; cfr[4 * nt + 1] = bb.y;
        cfr[4 * nt + 2] = bb.x; cfr[4 * nt + 3] = bb.y;
    }
    gemm_frag<KT, NTP>(cfr, hw, HS, g_W1s_hi, g_W1s_lo, lane);
    #pragma unroll
    for (int nt = 0; nt < NT; nt++) {
        float4 v; v.x = cfr[4 * nt]; v.y = cfr[4 * nt + 1];
        v.z = cfr[4 * nt + 2]; v.w = cfr[4 * nt + 3];
        *(float4*)(s1p + nt * 128 + lane * 4) = v;
    }
    __syncwarp();

    // ---- 30 diffusion steps (warps fully independent) ----
    #pragma unroll 1
    for (int s = 0; s < NSTEP; s++) {
        const float t = (float)(NSTEP - 1 - s);

        // L1: C = S1 + t*w385; += x @ W1x; LN+ReLU -> h
        #pragma unroll
        for (int nt = 0; nt < NT; nt++) {
            const float4 sv = *(const float4*)(s1p + nt * 128 + lane * 4);
            const float2 wv = *(const float2*)(cb + 6 * 256 + nt * 8 + 2 * q);
            cfr[4 * nt]     = fmaf(t, wv.x, sv.x);
            cfr[4 * nt + 1] = fmaf(t, wv.y, sv.y);
            cfr[4 * nt + 2] = fmaf(t, wv.x, sv.z);
            cfr[4 * nt + 3] = fmaf(t, wv.y, sv.w);
        }
        gemm_frag<KT1, NTP>(cfr, xw, XS, g_W1x_hi, g_W1x_lo, lane);
        __syncwarp();
        ln_relu_frag(cfr, hw, cb + 0 * 256, cb + 1 * 256, lane);
        __syncwarp();

        // L2: C = b2; += h @ W2; LN+ReLU -> h
        #pragma unroll
        for (int nt = 0; nt < NT; nt++) {
            const float2 bb = *(const float2*)(cb + 4 * 256 + nt * 8 + 2 * q);
            cfr[4 * nt] = bb.x; cfr[4 * nt + 1] = bb.y;
            cfr[4 * nt + 2] = bb.x; cfr[4 * nt + 3] = bb.y;
        }
        gemm_frag<KT, NTP>(cfr, hw, HS, g_W2_hi, g_W2_lo, lane);
        __syncwarp();
        ln_relu_frag(cfr, hw, cb + 2 * 256, cb + 3 * 256, lane);
        __syncwarp();

        // L3: C = b3p; += h @ W3; x -= 0.1*C
        #pragma unroll
        for (int nt = 0; nt < NT3; nt++) {
            const float2 bb = *(const float2*)(cb + 5 * 256 + nt * 8 + 2 * q);
            cfr[4 * nt] = bb.x; cfr[4 * nt + 1] = bb.y;
            cfr[4 * nt + 2] = bb.x; cfr[4 * nt + 3] = bb.y;
        }
        gemm_frag<KT, NTP3>(cfr, hw, HS, g_W3_hi, g_W3_lo, lane);
        __syncwarp();
        #pragma unroll
        for (int nt = 0; nt < 17; nt++) {      // cols 0..135 (x buffer has 140)
            const int col = nt * 8 + 2 * q;
            xw[tq * XS + col]           -= 0.1f * cfr[4 * nt];
            xw[tq * XS + col + 1]       -= 0.1f * cfr[4 * nt + 1];
            xw[(tq + 8) * XS + col]     -= 0.1f * cfr[4 * nt + 2];
            xw[(tq + 8) * XS + col + 1] -= 0.1f * cfr[4 * nt + 3];
        }
        __syncwarp();
    }

    // ---- epilogue: masked gumbel softmax argmax (straight-through) + tanh ----
    #pragma unroll 1
    for (int i = 0; i < WROWS; i++) {
        const size_t gr = grow0 + wr + i;
        const int c0 = lane * 4;
        const float4 xv = *(const float4*)(xw + i * XS + c0);
        const float4 mk = *(const float4*)(amask  + gr * 128 + c0);
        const float4 gn = *(const float4*)(gumbel + gr * 128 + c0);
        float z[4];
        z[0] = xv.x + (1.0f - mk.x) * (-1e9f) + gn.x;
        z[1] = xv.y + (1.0f - mk.y) * (-1e9f) + gn.y;
        z[2] = xv.z + (1.0f - mk.z) * (-1e9f) + gn.z;
        z[3] = xv.w + (1.0f - mk.w) * (-1e9f) + gn.w;
        float best = z[0]; int bi = c0;
        #pragma unroll
        for (int j = 1; j < 4; j++) if (z[j] > best) { best = z[j]; bi = c0 + j; }
        #pragma unroll
        for (int o = 16; o > 0; o >>= 1) {
            float ov = __shfl_xor_sync(0xffffffffu, best, o);
            int   oi = __shfl_xor_sync(0xffffffffu, bi,   o);
            if (ov > best || (ov == best && oi < bi)) { best = ov; bi = oi; }
        }
        float e[4]; float sl = 0.0f;
        #pragma unroll
        for (int j = 0; j < 4; j++) { e[j] = expf(z[j] - best); sl += e[j]; }
        #pragma unroll
        for (int o = 16; o > 0; o >>= 1) sl += __shfl_xor_sync(0xffffffffu, sl, o);
        #pragma unroll
        for (int j = 0; j < 4; j++) {
            const float p  = e[j] / sl;
            const float yh = (c0 + j == bi) ? 1.0f : 0.0f;
            const float tv = yh + p;
            out[gr * ADIM + c0 + j] = tv - p;
        }
        if (lane == 0) out[gr * ADIM + 128] = tanhf(xw[i * XS + 128]);
    }
}

extern "C" void kernel_launch(void* const* d_in, const int* in_sizes, int n_in,
                              void* d_out, int out_size)
{
    const float* state  = (const float*)d_in[0];
    const float* amask  = (const float*)d_in[1];
    const float* x_init = (const float*)d_in[2];
    const float* gumbel = (const float*)d_in[3];
    const float* W1     = (const float*)d_in[4];
    const float* b1     = (const float*)d_in[5];
    const float* g1     = (const float*)d_in[6];
    const float* be1    = (const float*)d_in[7];
    const float* W2     = (const float*)d_in[8];
    const float* b2     = (const float*)d_in[9];
    const float* g2     = (const float*)d_in[10];
    const float* be2    = (const float*)d_in[11];
    const float* W3     = (const float*)d_in[12];
    const float* b3     = (const float*)d_in[13];
    float* out          = (float*)d_out;

    // pack weight fragments (hi/lo tf32 split, mma frag order); dst via selector
    {
        int tot;
        tot = KT * NTP * 32;
        pack_frag<<<(tot + 255) / 256, 256>>>(W1, 0, HID, 256, 256, KT, NTP, 0);
        tot = KT1 * NTP * 32;
        pack_frag<<<(tot + 255) / 256, 256>>>(W1, 1, HID, 129, 256, KT1, NTP, SDIM);
        tot = KT * NTP * 32;
        pack_frag<<<(tot + 255) / 256, 256>>>(W2, 2, HID, 256, 256, KT, NTP, 0);
        tot = KT * NTP3 * 32;
        pack_frag<<<(tot + 255) / 256, 256>>>(W3, 3, ADIM, 256, 129, KT, NTP3, 0);
        pack_b3<<<1, 256>>>(b3);
    }

    cudaFuncSetAttribute(actor_kernel,
                         cudaFuncAttributeMaxDynamicSharedMemorySize,
                         (int)SMEM_BYTES);

    actor_kernel<<<NROWS / TM, 128, SMEM_BYTES>>>(
        state, amask, x_init, gumbel,
        W1, b1, g1, be1, W2, b2, g2, be2, b3, out);
}